// round 16
// baseline (speedup 1.0000x reference)
#include <cuda_runtime.h>
#include <cuda_bf16.h>
#include <cstdint>

#define BB   4
#define NPTS 16384
#define SSZ  2048
#define C1   128
#define C2   256
#define CIN  384
#define CH   256
#define ROWS (BB*NPTS)   // 65536

// ---------------------------------------------------------------------------
// Scratch. A-side: 2 planes per row [hi(K) | lo(K)].
// W-side: 3 planes per row [hi(K) | lo(K) | hi(K)].
// GEMM chunk map: ck in [0,KC): Ahi*Whi; [KC,2KC): Ahi*Wlo; [2KC,3KC): Alo*Whi.
// ---------------------------------------------------------------------------
__device__ __nv_bfloat16 g_a1[(size_t)ROWS * 2 * CIN];  // 100 MB
__device__ __nv_bfloat16 g_x [(size_t)ROWS * 2 * CH];   // 67 MB
__device__ float         g_y [(size_t)ROWS * CH];       // 67 MB
__device__ __nv_bfloat16 g_w1[CH * 3 * CIN];
__device__ __nv_bfloat16 g_w2[CH * 3 * CH];
__device__ float g_stats1[2 * CH];
__device__ float g_stats2[2 * CH];

// ---------------------------------------------------------------------------
// PTX helpers (compute_103-safe)
// ---------------------------------------------------------------------------
__device__ __forceinline__ uint32_t smem_u32(const void* p) {
    uint32_t a;
    asm("{ .reg .u64 t; cvta.to.shared.u64 t, %1; cvt.u32.u64 %0, t; }"
        : "=r"(a) : "l"(p));
    return a;
}

__device__ __forceinline__ void cp16(uint32_t dst, const void* src) {
    asm volatile("cp.async.cg.shared.global [%0], [%1], 16;" :: "r"(dst), "l"(src));
}

__device__ __forceinline__ void ldsm_x4(uint32_t* r, uint32_t addr) {
    asm volatile("ldmatrix.sync.aligned.m8n8.x4.shared.b16 {%0,%1,%2,%3}, [%4];"
        : "=r"(r[0]), "=r"(r[1]), "=r"(r[2]), "=r"(r[3]) : "r"(addr));
}

__device__ __forceinline__ void mma16816(float* d, const uint32_t* a, const uint32_t* b) {
    asm volatile(
        "mma.sync.aligned.m16n8k16.row.col.f32.bf16.bf16.f32 "
        "{%0,%1,%2,%3}, {%4,%5,%6,%7}, {%8,%9}, {%0,%1,%2,%3};"
        : "+f"(d[0]), "+f"(d[1]), "+f"(d[2]), "+f"(d[3])
        : "r"(a[0]), "r"(a[1]), "r"(a[2]), "r"(a[3]), "r"(b[0]), "r"(b[1]));
}

__device__ __forceinline__ void split_bf16(float o, __nv_bfloat16& h, __nv_bfloat16& l) {
    h = __float2bfloat16(o);
    l = __float2bfloat16(o - __bfloat162float(h));
}

// ---------------------------------------------------------------------------
// W1 -> 3-plane [hi|lo|hi], plus zero both stats arrays (block 0).
// ---------------------------------------------------------------------------
__global__ void __launch_bounds__(256) conv_w1_zero_kernel(
    const float* __restrict__ W, __nv_bfloat16* __restrict__ out)
{
    if (blockIdx.x == 0) {
        g_stats1[threadIdx.x] = 0.0f;
        g_stats1[256 + threadIdx.x] = 0.0f;
        g_stats2[threadIdx.x] = 0.0f;
        g_stats2[256 + threadIdx.x] = 0.0f;
    }
    int i = blockIdx.x * 256 + threadIdx.x;
    if (i < CH * CIN) {
        int o = i / CIN, k = i % CIN;
        float w = W[i];
        __nv_bfloat16 h, l;
        split_bf16(w, h, l);
        __nv_bfloat16* base = out + (size_t)o * (3 * CIN) + k;
        base[0]       = h;
        base[CIN]     = l;
        base[2 * CIN] = h;
    }
}

__global__ void __launch_bounds__(256) conv_w2_kernel(
    const float* __restrict__ W, __nv_bfloat16* __restrict__ out)
{
    int i = blockIdx.x * 256 + threadIdx.x;
    if (i < CH * CH) {
        int o = i / CH, k = i % CH;
        float w = W[i];
        __nv_bfloat16 h, l;
        split_bf16(w, h, l);
        __nv_bfloat16* base = out + (size_t)o * (3 * CH) + k;
        base[0]      = h;
        base[CH]     = l;
        base[2 * CH] = h;
    }
}

// ---------------------------------------------------------------------------
// pf1 -> 2-plane cols [0,128) of g_a1  (2 float4 per thread, higher MLP)
// ---------------------------------------------------------------------------
__global__ void __launch_bounds__(256) conv_pf1_kernel(
    const float* __restrict__ pf1, __nv_bfloat16* __restrict__ a1)
{
    int base_i = blockIdx.x * 512 + threadIdx.x;
    #pragma unroll
    for (int r = 0; r < 2; ++r) {
        int i = base_i + r * 256;              // float4 index over ROWS*C1/4
        int row = i >> 5;
        int c4 = (i & 31) * 4;
        float4 v = ((const float4*)pf1)[i];
        float o[4] = {v.x, v.y, v.z, v.w};
        __nv_bfloat16 h[4], l[4];
        #pragma unroll
        for (int j = 0; j < 4; ++j) split_bf16(o[j], h[j], l[j]);
        __nv_bfloat16* base = a1 + (size_t)row * (2 * CIN) + c4;
        *(__nv_bfloat162*)(base)           = __halves2bfloat162(h[0], h[1]);
        *(__nv_bfloat162*)(base + 2)       = __halves2bfloat162(h[2], h[3]);
        *(__nv_bfloat162*)(base + CIN)     = __halves2bfloat162(l[0], l[1]);
        *(__nv_bfloat162*)(base + CIN + 2) = __halves2bfloat162(l[2], l[3]);
    }
}

// ---------------------------------------------------------------------------
// KNN (k=3) + IDW interpolation -> 2-plane cols [128,384) of g_a1.
// 8 lanes per query, 2 queries per thread, lex-merge via 3 shfl_xor rounds.
// 64 queries/block, 256 threads, grid 256x4 = 1024 blocks.  (R13 config.)
// ---------------------------------------------------------------------------
#define QP8 257   // float4 stride per eighth (pad -> 8 bcast reads tile banks)

__device__ __forceinline__ bool lex_less(float da, int ia, float db, int ib) {
    return (da < db) || (da == db && ia < ib);
}

__global__ void __launch_bounds__(256, 5) knn_interp_kernel(
    const float* __restrict__ p1, const float* __restrict__ p2,
    const float* __restrict__ pf2, __nv_bfloat16* __restrict__ a1)
{
    __shared__ float4 sp[8 * QP8];
    const int b = blockIdx.y;
    const int tid = threadIdx.x;
    const int c    = tid & 7;         // eighth 0..7
    const int slot = tid >> 3;        // 0..31

    for (int i = tid; i < SSZ; i += 256) {
        float x = p2[(b * SSZ + i) * 3 + 0];
        float y = p2[(b * SSZ + i) * 3 + 1];
        float z = p2[(b * SSZ + i) * 3 + 2];
        sp[(i >> 8) * QP8 + (i & 255)] = make_float4(x, y, z, x*x + y*y + z*z);
    }
    __syncthreads();

    int n[2], q[2];
    n[0] = blockIdx.x * 64 + slot;  n[1] = n[0] + 32;
    q[0] = b * NPTS + n[0];         q[1] = b * NPTS + n[1];

    float qx[2], qy[2], qz[2], sq1[2];
    #pragma unroll
    for (int u = 0; u < 2; ++u) {
        qx[u] = p1[q[u]*3+0]; qy[u] = p1[q[u]*3+1]; qz[u] = p1[q[u]*3+2];
        sq1[u] = qx[u]*qx[u] + qy[u]*qy[u] + qz[u]*qz[u];
    }

    float d0[2] = {1e30f, 1e30f}, d1[2] = {1e30f, 1e30f}, d2[2] = {1e30f, 1e30f};
    int   i0[2] = {0, 0},         i1[2] = {0, 0},         i2[2] = {0, 0};

    const float4* spq = sp + c * QP8;
    const int base_idx = c * 256;

    #pragma unroll 4
    for (int s = 0; s < 256; ++s) {
        float4 t = spq[s];
        #pragma unroll
        for (int u = 0; u < 2; ++u) {
            float dot = fmaf(qx[u], t.x, fmaf(qy[u], t.y, qz[u] * t.z));
            float d = sq1[u] + t.w - 2.0f * dot;    // same arithmetic as R1
            if (d < d2[u]) {
                int gi = base_idx + s;
                if (d < d1[u]) {
                    d2[u] = d1[u]; i2[u] = i1[u];
                    if (d < d0[u]) { d1[u] = d0[u]; i1[u] = i0[u]; d0[u] = d; i0[u] = gi; }
                    else           { d1[u] = d;  i1[u] = gi; }
                } else { d2[u] = d; i2[u] = gi; }
            }
        }
    }

    #pragma unroll
    for (int u = 0; u < 2; ++u) {
        #pragma unroll
        for (int w = 1; w <= 4; w <<= 1) {
            float e0 = __shfl_xor_sync(0xffffffffu, d0[u], w);
            float e1 = __shfl_xor_sync(0xffffffffu, d1[u], w);
            float e2 = __shfl_xor_sync(0xffffffffu, d2[u], w);
            int   j0 = __shfl_xor_sync(0xffffffffu, i0[u], w);
            int   j1 = __shfl_xor_sync(0xffffffffu, i1[u], w);
            int   j2 = __shfl_xor_sync(0xffffffffu, i2[u], w);
            #pragma unroll
            for (int e = 0; e < 3; ++e) {
                float dd = (e == 0) ? e0 : (e == 1) ? e1 : e2;
                int   jj = (e == 0) ? j0 : (e == 1) ? j1 : j2;
                if (lex_less(dd, jj, d2[u], i2[u])) {
                    if (lex_less(dd, jj, d1[u], i1[u])) {
                        d2[u] = d1[u]; i2[u] = i1[u];
                        if (lex_less(dd, jj, d0[u], i0[u])) {
                            d1[u] = d0[u]; i1[u] = i0[u]; d0[u] = dd; i0[u] = jj;
                        } else { d1[u] = dd; i1[u] = jj; }
                    } else { d2[u] = dd; i2[u] = jj; }
                }
            }
        }
    }

    #pragma unroll
    for (int u = 0; u < 2; ++u) {
        float r0 = 1.0f / (d0[u] + 1e-8f);
        float r1 = 1.0f / (d1[u] + 1e-8f);
        float r2 = 1.0f / (d2[u] + 1e-8f);
        float inv = 1.0f / (r0 + r1 + r2);
        float w0 = r0 * inv, w1 = r1 * inv, w2 = r2 * inv;

        const float4* f0 = (const float4*)(pf2 + (size_t)(b * SSZ + i0[u]) * C2) + c * 8;
        const float4* f1 = (const float4*)(pf2 + (size_t)(b * SSZ + i1[u]) * C2) + c * 8;
        const float4* f2 = (const float4*)(pf2 + (size_t)(b * SSZ + i2[u]) * C2) + c * 8;
        __nv_bfloat16* obase = a1 + (size_t)q[u] * (2 * CIN) + C1 + c * 32;

        #pragma unroll 4
        for (int k = 0; k < 8; ++k) {
            float4 a = f0[k], bv = f1[k], cv = f2[k];
            float o[4];
            o[0] = w0*a.x + w1*bv.x + w2*cv.x;
            o[1] = w0*a.y + w1*bv.y + w2*cv.y;
            o[2] = w0*a.z + w1*bv.z + w2*cv.z;
            o[3] = w0*a.w + w1*bv.w + w2*cv.w;
            __nv_bfloat16 h[4], l[4];
            #pragma unroll
            for (int j = 0; j < 4; ++j) split_bf16(o[j], h[j], l[j]);
            *(__nv_bfloat162*)(obase + k*4)           = __halves2bfloat162(h[0], h[1]);
            *(__nv_bfloat162*)(obase + k*4 + 2)       = __halves2bfloat162(h[2], h[3]);
            *(__nv_bfloat162*)(obase + CIN + k*4)     = __halves2bfloat162(l[0], l[1]);
            *(__nv_bfloat162*)(obase + CIN + k*4 + 2) = __halves2bfloat162(l[2], l[3]);
        }
    }
}

// ---------------------------------------------------------------------------
// bf16 pipelined GEMM, plane-mapped chunks, fused BN-stats epilogue.
// CTA tile 128x128, 128 threads (4 warps 2x2), warp tile 64x64.
// 3-stage cp.async, single sync per chunk. 2 CTAs/SM.
// Issue model: 512 mma / (512 + 128 ldsm + 128 cp + sync) -> ~65% tensor.
// ---------------------------------------------------------------------------
template <int K>
__global__ void __launch_bounds__(128, 2) gemm_fused_kernel(
    const __nv_bfloat16* __restrict__ A, const __nv_bfloat16* __restrict__ W,
    float* __restrict__ Y, float* __restrict__ stats)
{
    constexpr int KC  = K / 64;          // chunks per plane product
    constexpr int NCC = 3 * KC;          // total chunks
    constexpr int KB_A = 4 * K;          // A row stride bytes (hi+lo)
    constexpr int KB_W = 6 * K;          // W row stride bytes (3 planes)
    constexpr int LD = 144;              // smem row stride bytes
    constexpr int A_SZ = 128 * LD;       // 18432
    constexpr int W_SZ = 128 * LD;       // 18432
    constexpr int STAGE = A_SZ + W_SZ;   // 36864

    extern __shared__ char smem[];
    const uint32_t sb = smem_u32(smem);
    const int tid  = threadIdx.x;
    const int wid  = tid >> 5;           // 0..3
    const int lane = tid & 31;
    const int rowBase = blockIdx.x * 128;
    const int colBase = blockIdx.y * 128;

    const int warp_m = wid & 1;          // 64 rows each
    const int warp_n = wid >> 1;         // 0..1, 64 cols each

    const char* bA = (const char*)A + (size_t)rowBase * KB_A;
    const char* bW = (const char*)W + (size_t)colBase * KB_W;

    float acc[4][8][4];
    #pragma unroll
    for (int i = 0; i < 4; ++i)
        #pragma unroll
        for (int j = 0; j < 8; ++j)
            #pragma unroll
            for (int k = 0; k < 4; ++k) acc[i][j][k] = 0.0f;

    auto load_chunk = [&](int ck, int s) {
        if (ck < NCC) {
            const uint32_t st = sb + (uint32_t)s * STAGE;
            const int pc = (ck >= 2 * KC) ? (ck - 2 * KC) : (ck >= KC ? ck - KC : ck);
            const int aoff = ((ck >= 2 * KC) ? 2 * K : 0) + pc * 128;
            const int woff = ck * 128;
            #pragma unroll
            for (int j = 0; j < 8; ++j) {                // A: 128 rows x 8x16B
                int v = tid + j * 128;
                int row = v >> 3, c = v & 7;
                cp16(st + row * LD + c * 16, bA + (size_t)row * KB_A + aoff + c * 16);
            }
            #pragma unroll
            for (int j = 0; j < 8; ++j) {                // W: 128 rows x 8x16B
                int v = tid + j * 128;
                int row = v >> 3, c = v & 7;
                cp16(st + A_SZ + row * LD + c * 16, bW + (size_t)row * KB_W + woff + c * 16);
            }
        }
        asm volatile("cp.async.commit_group;" ::: "memory");
    };

    load_chunk(0, 0);
    load_chunk(1, 1);

    const int a_row = (lane & 15);
    const int a_k8  = (lane >> 4) << 3;
    const int b_row = (lane & 7) + ((lane >> 4) << 3);
    const int b_k8  = ((lane >> 3) & 1) << 3;

    for (int ck = 0; ck < NCC; ++ck) {
        const int s = ck % 3;
        asm volatile("cp.async.wait_group 1;" ::: "memory");
        __syncthreads();

        // Prefetch chunk ck+2 into slot (ck+2)%3 — consumed at ck-1, safe.
        load_chunk(ck + 2, (ck + 2) % 3);

        const uint32_t aA = sb + (uint32_t)s * STAGE;
        const uint32_t aW = aA + A_SZ;

        #pragma unroll
        for (int kk = 0; kk < 4; ++kk) {
            const uint32_t kbA = (uint32_t)((kk * 16 + a_k8) * 2);
            const uint32_t kbB = (uint32_t)((kk * 16 + b_k8) * 2);

            uint32_t bb[16];
            #pragma unroll
            for (int g = 0; g < 4; ++g) {                // four n16 groups
                uint32_t nn = (uint32_t)(warp_n * 64 + g * 16 + b_row);
                ldsm_x4(bb + g * 4, aW + nn * LD + kbB);
            }
            #pragma unroll
            for (int mt = 0; mt < 4; ++mt) {
                uint32_t m = (uint32_t)(warp_m * 64 + mt * 16 + a_row);
                uint32_t aa[4];
                ldsm_x4(aa, aA + m * LD + kbA);
                #pragma unroll
                for (int nt = 0; nt < 8; ++nt)
                    mma16816(acc[mt][nt], aa, bb + nt * 2);
            }
        }
    }

    // ---- Epilogue 1: write Y ----
    const int er = lane >> 2;
    const int ec = (lane & 3) * 2;
    #pragma unroll
    for (int mt = 0; mt < 4; ++mt) {
        const int row = rowBase + warp_m * 64 + mt * 16 + er;
        #pragma unroll
        for (int nt = 0; nt < 8; ++nt) {
            const int col = colBase + warp_n * 64 + nt * 8 + ec;
            *(float2*)(Y + (size_t)row * CH + col) =
                make_float2(acc[mt][nt][0], acc[mt][nt][1]);
            *(float2*)(Y + (size_t)(row + 8) * CH + col) =
                make_float2(acc[mt][nt][2], acc[mt][nt][3]);
        }
    }

    // ---- Epilogue 2: fused BN stats (sum, sumsq per channel) ----
    #pragma unroll
    for (int nt = 0; nt < 8; ++nt) {
        #pragma unroll
        for (int j = 0; j < 2; ++j) {
            float s = 0.0f, q = 0.0f;
            #pragma unroll
            for (int mt = 0; mt < 4; ++mt) {
                float u0 = acc[mt][nt][j];
                float u1 = acc[mt][nt][j + 2];
                s += u0 + u1;
                q = fmaf(u0, u0, q);
                q = fmaf(u1, u1, q);
            }
            s += __shfl_down_sync(0xffffffffu, s, 16);
            q += __shfl_down_sync(0xffffffffu, q, 16);
            s += __shfl_down_sync(0xffffffffu, s, 8);
            q += __shfl_down_sync(0xffffffffu, q, 8);
            s += __shfl_down_sync(0xffffffffu, s, 4);
            q += __shfl_down_sync(0xffffffffu, q, 4);
            if ((lane >> 2) == 0) {
                int col = colBase + warp_n * 64 + nt * 8 + ec + j;
                atomicAdd(&stats[col], s);
                atomicAdd(&stats[CH + col], q);
            }
        }
    }
}

// ---------------------------------------------------------------------------
// BN+ReLU, output 2-plane bf16 (layer1 -> layer2 input)
// ---------------------------------------------------------------------------
__global__ void __launch_bounds__(256) bnrelu_split_kernel(
    const float* __restrict__ Y,
    const float* __restrict__ gamma, const float* __restrict__ beta,
    __nv_bfloat16* __restrict__ X)
{
    __shared__ float sc[CH], bi[CH];
    const int t = threadIdx.x;
    {
        const float invM = 1.0f / (float)ROWS;
        float mean = g_stats1[t] * invM;
        float var  = g_stats1[CH + t] * invM - mean * mean;
        float s = rsqrtf(var + 1e-5f) * gamma[t];
        sc[t] = s;
        bi[t] = beta[t] - mean * s;
    }
    __syncthreads();

    const int total = ROWS * CH / 4;
    for (int i = blockIdx.x * 256 + t; i < total; i += gridDim.x * 256) {
        float4 v = ((const float4*)Y)[i];
        int row = i >> 6;
        int c0 = (i & 63) * 4;
        float o[4];
        o[0] = fmaxf(fmaf(v.x, sc[c0+0], bi[c0+0]), 0.0f);
        o[1] = fmaxf(fmaf(v.y, sc[c0+1], bi[c0+1]), 0.0f);
        o[2] = fmaxf(fmaf(v.z, sc[c0+2], bi[c0+2]), 0.0f);
        o[3] = fmaxf(fmaf(v.w, sc[c0+3], bi[c0+3]), 0.0f);
        __nv_bfloat16 h[4], l[4];
        #pragma unroll
        for (int j = 0; j < 4; ++j) split_bf16(o[j], h[j], l[j]);
        __nv_bfloat16* base = X + (size_t)row * (2 * CH) + c0;
        *(__nv_bfloat162*)(base)          = __halves2bfloat162(h[0], h[1]);
        *(__nv_bfloat162*)(base + 2)      = __halves2bfloat162(h[2], h[3]);
        *(__nv_bfloat162*)(base + CH)     = __halves2bfloat162(l[0], l[1]);
        *(__nv_bfloat162*)(base + CH + 2) = __halves2bfloat162(l[2], l[3]);
    }
}

// ---------------------------------------------------------------------------
// BN+ReLU in place (layer2 final, fp32)
// ---------------------------------------------------------------------------
__global__ void __launch_bounds__(256) bnrelu_inplace_kernel(
    float* __restrict__ X,
    const float* __restrict__ gamma, const float* __restrict__ beta)
{
    __shared__ float sc[CH], bi[CH];
    const int t = threadIdx.x;
    {
        const float invM = 1.0f / (float)ROWS;
        float mean = g_stats2[t] * invM;
        float var  = g_stats2[CH + t] * invM - mean * mean;
        float s = rsqrtf(var + 1e-5f) * gamma[t];
        sc[t] = s;
        bi[t] = beta[t] - mean * s;
    }
    __syncthreads();

    const int total = ROWS * CH / 4;
    for (int i = blockIdx.x * 256 + t; i < total; i += gridDim.x * 256) {
        float4 v = ((float4*)X)[i];
        int c0 = (i * 4) & (CH - 1);
        v.x = fmaxf(fmaf(v.x, sc[c0+0], bi[c0+0]), 0.0f);
        v.y = fmaxf(fmaf(v.y, sc[c0+1], bi[c0+1]), 0.0f);
        v.z = fmaxf(fmaf(v.z, sc[c0+2], bi[c0+2]), 0.0f);
        v.w = fmaxf(fmaf(v.w, sc[c0+3], bi[c0+3]), 0.0f);
        ((float4*)X)[i] = v;
    }
}

// ---------------------------------------------------------------------------
// Launcher (graph-capturable). Side stream overlaps the conversions with KNN.
// ---------------------------------------------------------------------------
extern "C" void kernel_launch(void* const* d_in, const int* in_sizes, int n_in,
                              void* d_out, int out_size)
{
    const float* p1     = (const float*)d_in[0];
    const float* p2     = (const float*)d_in[1];
    const float* pf1    = (const float*)d_in[2];
    const float* pf2    = (const float*)d_in[3];
    const float* W1     = (const float*)d_in[4];
    const float* gamma1 = (const float*)d_in[5];
    const float* beta1  = (const float*)d_in[6];
    const float* W2     = (const float*)d_in[7];
    const float* gamma2 = (const float*)d_in[8];
    const float* beta2  = (const float*)d_in[9];
    float* out = (float*)d_out;

    __nv_bfloat16 *a1, *x, *w1, *w2;
    float *y, *st1, *st2;
    cudaGetSymbolAddress((void**)&a1, g_a1);
    cudaGetSymbolAddress((void**)&x,  g_x);
    cudaGetSymbolAddress((void**)&w1, g_w1);
    cudaGetSymbolAddress((void**)&w2, g_w2);
    cudaGetSymbolAddress((void**)&y,  g_y);
    cudaGetSymbolAddress((void**)&st1, g_stats1);
    cudaGetSymbolAddress((void**)&st2, g_stats2);

    const int GEMM_SMEM = 3 * 36864;   // 110592 bytes -> 2 CTAs/SM
    cudaFuncSetAttribute(gemm_fused_kernel<CIN>,
                         cudaFuncAttributeMaxDynamicSharedMemorySize, GEMM_SMEM);
    cudaFuncSetAttribute(gemm_fused_kernel<CH>,
                         cudaFuncAttributeMaxDynamicSharedMemorySize, GEMM_SMEM);

    static cudaStream_t side = nullptr;
    static cudaEvent_t evFork = nullptr, evJoin = nullptr;
    if (side == nullptr) {
        cudaStreamCreateWithFlags(&side, cudaStreamNonBlocking);
        cudaEventCreateWithFlags(&evFork, cudaEventDisableTiming);
        cudaEventCreateWithFlags(&evJoin, cudaEventDisableTiming);
    }

    // Fork: side stream joins the (possibly capturing) main stream
    cudaEventRecord(evFork, 0);
    cudaStreamWaitEvent(side, evFork, 0);

    // Side branch: conversions (disjoint from KNN outputs)
    conv_w1_zero_kernel<<<(CH * CIN + 255) / 256, 256, 0, side>>>(W1, w1);
    conv_pf1_kernel<<<ROWS * C1 / 4 / 512, 256, 0, side>>>(pf1, a1);
    conv_w2_kernel<<<(CH * CH + 255) / 256, 256, 0, side>>>(W2, w2);
    cudaEventRecord(evJoin, side);

    // Main branch: KNN + interp (concurrent with conversions)
    knn_interp_kernel<<<dim3(NPTS / 64, BB), 256>>>(p1, p2, pf2, a1);

    // Join
    cudaStreamWaitEvent(0, evJoin, 0);

    // layer-1 GEMM (128 threads, warp tile 64x64)
    gemm_fused_kernel<CIN><<<dim3(ROWS / 128, CH / 128), 128, GEMM_SMEM>>>(a1, w1, y, st1);
    // BN+ReLU -> 2-plane x
    bnrelu_split_kernel<<<2048, 256>>>(y, gamma1, beta1, x);
    // layer-2 GEMM -> d_out (pre-activation)
    gemm_fused_kernel<CH><<<dim3(ROWS / 128, CH / 128), 128, GEMM_SMEM>>>(x, w2, out, st2);
    // final BN+ReLU in place
    bnrelu_inplace_kernel<<<2048, 256>>>(out, gamma2, beta2);
}

// round 17
// speedup vs baseline: 1.1147x; 1.1147x over previous
#include <cuda_runtime.h>
#include <cuda_bf16.h>
#include <cstdint>

#define BB   4
#define NPTS 16384
#define SSZ  2048
#define C1   128
#define C2   256
#define CIN  384
#define CH   256
#define ROWS (BB*NPTS)   // 65536

// ---------------------------------------------------------------------------
// Scratch. A-side: 2 planes per row [hi(K) | lo(K)].
// W-side: 3 planes per row [hi(K) | lo(K) | hi(K)].
// GEMM chunk map: ck in [0,KC): Ahi*Whi; [KC,2KC): Ahi*Wlo; [2KC,3KC): Alo*Whi.
// ---------------------------------------------------------------------------
__device__ __nv_bfloat16 g_a1[(size_t)ROWS * 2 * CIN];  // 100 MB
__device__ __nv_bfloat16 g_x [(size_t)ROWS * 2 * CH];   // 67 MB
__device__ float         g_y [(size_t)ROWS * CH];       // 67 MB
__device__ __nv_bfloat16 g_w1[CH * 3 * CIN];
__device__ __nv_bfloat16 g_w2[CH * 3 * CH];
__device__ float g_stats1[2 * CH];
__device__ float g_stats2[2 * CH];

// ---------------------------------------------------------------------------
// PTX helpers (compute_103-safe)
// ---------------------------------------------------------------------------
__device__ __forceinline__ uint32_t smem_u32(const void* p) {
    uint32_t a;
    asm("{ .reg .u64 t; cvta.to.shared.u64 t, %1; cvt.u32.u64 %0, t; }"
        : "=r"(a) : "l"(p));
    return a;
}

__device__ __forceinline__ void cp16(uint32_t dst, const void* src) {
    asm volatile("cp.async.cg.shared.global [%0], [%1], 16;" :: "r"(dst), "l"(src));
}

__device__ __forceinline__ void ldsm_x4(uint32_t* r, uint32_t addr) {
    asm volatile("ldmatrix.sync.aligned.m8n8.x4.shared.b16 {%0,%1,%2,%3}, [%4];"
        : "=r"(r[0]), "=r"(r[1]), "=r"(r[2]), "=r"(r[3]) : "r"(addr));
}

__device__ __forceinline__ void mma16816(float* d, const uint32_t* a, const uint32_t* b) {
    asm volatile(
        "mma.sync.aligned.m16n8k16.row.col.f32.bf16.bf16.f32 "
        "{%0,%1,%2,%3}, {%4,%5,%6,%7}, {%8,%9}, {%0,%1,%2,%3};"
        : "+f"(d[0]), "+f"(d[1]), "+f"(d[2]), "+f"(d[3])
        : "r"(a[0]), "r"(a[1]), "r"(a[2]), "r"(a[3]), "r"(b[0]), "r"(b[1]));
}

__device__ __forceinline__ void split_bf16(float o, __nv_bfloat16& h, __nv_bfloat16& l) {
    h = __float2bfloat16(o);
    l = __float2bfloat16(o - __bfloat162float(h));
}

// ---------------------------------------------------------------------------
// W1 -> 3-plane [hi|lo|hi], plus zero both stats arrays (block 0).
// ---------------------------------------------------------------------------
__global__ void __launch_bounds__(256) conv_w1_zero_kernel(
    const float* __restrict__ W, __nv_bfloat16* __restrict__ out)
{
    if (blockIdx.x == 0) {
        g_stats1[threadIdx.x] = 0.0f;
        g_stats1[256 + threadIdx.x] = 0.0f;
        g_stats2[threadIdx.x] = 0.0f;
        g_stats2[256 + threadIdx.x] = 0.0f;
    }
    int i = blockIdx.x * 256 + threadIdx.x;
    if (i < CH * CIN) {
        int o = i / CIN, k = i % CIN;
        float w = W[i];
        __nv_bfloat16 h, l;
        split_bf16(w, h, l);
        __nv_bfloat16* base = out + (size_t)o * (3 * CIN) + k;
        base[0]       = h;
        base[CIN]     = l;
        base[2 * CIN] = h;
    }
}

__global__ void __launch_bounds__(256) conv_w2_kernel(
    const float* __restrict__ W, __nv_bfloat16* __restrict__ out)
{
    int i = blockIdx.x * 256 + threadIdx.x;
    if (i < CH * CH) {
        int o = i / CH, k = i % CH;
        float w = W[i];
        __nv_bfloat16 h, l;
        split_bf16(w, h, l);
        __nv_bfloat16* base = out + (size_t)o * (3 * CH) + k;
        base[0]      = h;
        base[CH]     = l;
        base[2 * CH] = h;
    }
}

// ---------------------------------------------------------------------------
// pf1 -> 2-plane cols [0,128) of g_a1  (2 float4 per thread, higher MLP)
// ---------------------------------------------------------------------------
__global__ void __launch_bounds__(256) conv_pf1_kernel(
    const float* __restrict__ pf1, __nv_bfloat16* __restrict__ a1)
{
    int base_i = blockIdx.x * 512 + threadIdx.x;
    #pragma unroll
    for (int r = 0; r < 2; ++r) {
        int i = base_i + r * 256;              // float4 index over ROWS*C1/4
        int row = i >> 5;
        int c4 = (i & 31) * 4;
        float4 v = ((const float4*)pf1)[i];
        float o[4] = {v.x, v.y, v.z, v.w};
        __nv_bfloat16 h[4], l[4];
        #pragma unroll
        for (int j = 0; j < 4; ++j) split_bf16(o[j], h[j], l[j]);
        __nv_bfloat16* base = a1 + (size_t)row * (2 * CIN) + c4;
        *(__nv_bfloat162*)(base)           = __halves2bfloat162(h[0], h[1]);
        *(__nv_bfloat162*)(base + 2)       = __halves2bfloat162(h[2], h[3]);
        *(__nv_bfloat162*)(base + CIN)     = __halves2bfloat162(l[0], l[1]);
        *(__nv_bfloat162*)(base + CIN + 2) = __halves2bfloat162(l[2], l[3]);
    }
}

// ---------------------------------------------------------------------------
// KNN (k=3) + IDW interpolation -> 2-plane cols [128,384) of g_a1.
// 8 lanes per query, 2 queries per thread, lex-merge via 3 shfl_xor rounds.
// 64 queries/block, 256 threads, grid 256x4 = 1024 blocks.  (R13 config.)
// ---------------------------------------------------------------------------
#define QP8 257   // float4 stride per eighth (pad -> 8 bcast reads tile banks)

__device__ __forceinline__ bool lex_less(float da, int ia, float db, int ib) {
    return (da < db) || (da == db && ia < ib);
}

__global__ void __launch_bounds__(256, 5) knn_interp_kernel(
    const float* __restrict__ p1, const float* __restrict__ p2,
    const float* __restrict__ pf2, __nv_bfloat16* __restrict__ a1)
{
    __shared__ float4 sp[8 * QP8];
    const int b = blockIdx.y;
    const int tid = threadIdx.x;
    const int c    = tid & 7;         // eighth 0..7
    const int slot = tid >> 3;        // 0..31

    for (int i = tid; i < SSZ; i += 256) {
        float x = p2[(b * SSZ + i) * 3 + 0];
        float y = p2[(b * SSZ + i) * 3 + 1];
        float z = p2[(b * SSZ + i) * 3 + 2];
        sp[(i >> 8) * QP8 + (i & 255)] = make_float4(x, y, z, x*x + y*y + z*z);
    }
    __syncthreads();

    int n[2], q[2];
    n[0] = blockIdx.x * 64 + slot;  n[1] = n[0] + 32;
    q[0] = b * NPTS + n[0];         q[1] = b * NPTS + n[1];

    float qx[2], qy[2], qz[2], sq1[2];
    #pragma unroll
    for (int u = 0; u < 2; ++u) {
        qx[u] = p1[q[u]*3+0]; qy[u] = p1[q[u]*3+1]; qz[u] = p1[q[u]*3+2];
        sq1[u] = qx[u]*qx[u] + qy[u]*qy[u] + qz[u]*qz[u];
    }

    float d0[2] = {1e30f, 1e30f}, d1[2] = {1e30f, 1e30f}, d2[2] = {1e30f, 1e30f};
    int   i0[2] = {0, 0},         i1[2] = {0, 0},         i2[2] = {0, 0};

    const float4* spq = sp + c * QP8;
    const int base_idx = c * 256;

    #pragma unroll 4
    for (int s = 0; s < 256; ++s) {
        float4 t = spq[s];
        #pragma unroll
        for (int u = 0; u < 2; ++u) {
            float dot = fmaf(qx[u], t.x, fmaf(qy[u], t.y, qz[u] * t.z));
            float d = sq1[u] + t.w - 2.0f * dot;    // same arithmetic as R1
            if (d < d2[u]) {
                int gi = base_idx + s;
                if (d < d1[u]) {
                    d2[u] = d1[u]; i2[u] = i1[u];
                    if (d < d0[u]) { d1[u] = d0[u]; i1[u] = i0[u]; d0[u] = d; i0[u] = gi; }
                    else           { d1[u] = d;  i1[u] = gi; }
                } else { d2[u] = d; i2[u] = gi; }
            }
        }
    }

    #pragma unroll
    for (int u = 0; u < 2; ++u) {
        #pragma unroll
        for (int w = 1; w <= 4; w <<= 1) {
            float e0 = __shfl_xor_sync(0xffffffffu, d0[u], w);
            float e1 = __shfl_xor_sync(0xffffffffu, d1[u], w);
            float e2 = __shfl_xor_sync(0xffffffffu, d2[u], w);
            int   j0 = __shfl_xor_sync(0xffffffffu, i0[u], w);
            int   j1 = __shfl_xor_sync(0xffffffffu, i1[u], w);
            int   j2 = __shfl_xor_sync(0xffffffffu, i2[u], w);
            #pragma unroll
            for (int e = 0; e < 3; ++e) {
                float dd = (e == 0) ? e0 : (e == 1) ? e1 : e2;
                int   jj = (e == 0) ? j0 : (e == 1) ? j1 : j2;
                if (lex_less(dd, jj, d2[u], i2[u])) {
                    if (lex_less(dd, jj, d1[u], i1[u])) {
                        d2[u] = d1[u]; i2[u] = i1[u];
                        if (lex_less(dd, jj, d0[u], i0[u])) {
                            d1[u] = d0[u]; i1[u] = i0[u]; d0[u] = dd; i0[u] = jj;
                        } else { d1[u] = dd; i1[u] = jj; }
                    } else { d2[u] = dd; i2[u] = jj; }
                }
            }
        }
    }

    #pragma unroll
    for (int u = 0; u < 2; ++u) {
        float r0 = 1.0f / (d0[u] + 1e-8f);
        float r1 = 1.0f / (d1[u] + 1e-8f);
        float r2 = 1.0f / (d2[u] + 1e-8f);
        float inv = 1.0f / (r0 + r1 + r2);
        float w0 = r0 * inv, w1 = r1 * inv, w2 = r2 * inv;

        const float4* f0 = (const float4*)(pf2 + (size_t)(b * SSZ + i0[u]) * C2) + c * 8;
        const float4* f1 = (const float4*)(pf2 + (size_t)(b * SSZ + i1[u]) * C2) + c * 8;
        const float4* f2 = (const float4*)(pf2 + (size_t)(b * SSZ + i2[u]) * C2) + c * 8;
        __nv_bfloat16* obase = a1 + (size_t)q[u] * (2 * CIN) + C1 + c * 32;

        #pragma unroll 4
        for (int k = 0; k < 8; ++k) {
            float4 a = f0[k], bv = f1[k], cv = f2[k];
            float o[4];
            o[0] = w0*a.x + w1*bv.x + w2*cv.x;
            o[1] = w0*a.y + w1*bv.y + w2*cv.y;
            o[2] = w0*a.z + w1*bv.z + w2*cv.z;
            o[3] = w0*a.w + w1*bv.w + w2*cv.w;
            __nv_bfloat16 h[4], l[4];
            #pragma unroll
            for (int j = 0; j < 4; ++j) split_bf16(o[j], h[j], l[j]);
            *(__nv_bfloat162*)(obase + k*4)           = __halves2bfloat162(h[0], h[1]);
            *(__nv_bfloat162*)(obase + k*4 + 2)       = __halves2bfloat162(h[2], h[3]);
            *(__nv_bfloat162*)(obase + CIN + k*4)     = __halves2bfloat162(l[0], l[1]);
            *(__nv_bfloat162*)(obase + CIN + k*4 + 2) = __halves2bfloat162(l[2], l[3]);
        }
    }
}

// ---------------------------------------------------------------------------
// bf16 pipelined GEMM, plane-mapped chunks, fused BN-stats epilogue.
// CTA tile 128x128, 256 threads (8 warps 2x4), warp tile 64x32.
// 3-stage cp.async, single sync per chunk; chunk loop FULLY UNROLLED
// (NCC compile-time) so stage offsets/plane offsets become immediates.
// ---------------------------------------------------------------------------
template <int K>
__global__ void __launch_bounds__(256, 2) gemm_fused_kernel(
    const __nv_bfloat16* __restrict__ A, const __nv_bfloat16* __restrict__ W,
    float* __restrict__ Y, float* __restrict__ stats)
{
    constexpr int KC  = K / 64;          // chunks per plane product
    constexpr int NCC = 3 * KC;          // total chunks
    constexpr int KB_A = 4 * K;          // A row stride bytes (hi+lo)
    constexpr int KB_W = 6 * K;          // W row stride bytes (3 planes)
    constexpr int LD = 144;              // smem row stride bytes
    constexpr int A_SZ = 128 * LD;       // 18432
    constexpr int W_SZ = 128 * LD;       // 18432
    constexpr int STAGE = A_SZ + W_SZ;   // 36864

    extern __shared__ char smem[];
    const uint32_t sb = smem_u32(smem);
    const int tid  = threadIdx.x;
    const int wid  = tid >> 5;
    const int lane = tid & 31;
    const int rowBase = blockIdx.x * 128;
    const int colBase = blockIdx.y * 128;

    const int warp_m = wid & 1;          // 64 rows each
    const int warp_n = wid >> 1;         // 0..3, 32 cols each

    const char* bA = (const char*)A + (size_t)rowBase * KB_A;
    const char* bW = (const char*)W + (size_t)colBase * KB_W;

    float acc[4][4][4];
    #pragma unroll
    for (int i = 0; i < 4; ++i)
        #pragma unroll
        for (int j = 0; j < 4; ++j)
            #pragma unroll
            for (int k = 0; k < 4; ++k) acc[i][j][k] = 0.0f;

    auto load_chunk = [&](int ck, int s) {
        if (ck < NCC) {
            const uint32_t st = sb + (uint32_t)s * STAGE;
            const int pc = (ck >= 2 * KC) ? (ck - 2 * KC) : (ck >= KC ? ck - KC : ck);
            const int aoff = ((ck >= 2 * KC) ? 2 * K : 0) + pc * 128;
            const int woff = ck * 128;
            #pragma unroll
            for (int j = 0; j < 4; ++j) {                // A: 128 rows x 8x16B
                int v = tid + j * 256;
                int row = v >> 3, c = v & 7;
                cp16(st + row * LD + c * 16, bA + (size_t)row * KB_A + aoff + c * 16);
            }
            #pragma unroll
            for (int j = 0; j < 4; ++j) {                // W: 128 rows x 8x16B
                int v = tid + j * 256;
                int row = v >> 3, c = v & 7;
                cp16(st + A_SZ + row * LD + c * 16, bW + (size_t)row * KB_W + woff + c * 16);
            }
        }
        asm volatile("cp.async.commit_group;" ::: "memory");
    };

    load_chunk(0, 0);
    load_chunk(1, 1);

    const int a_row = (lane & 15);
    const int a_k8  = (lane >> 4) << 3;
    const int b_row = (lane & 7) + ((lane >> 4) << 3);
    const int b_k8  = ((lane >> 3) & 1) << 3;

    #pragma unroll
    for (int ck = 0; ck < NCC; ++ck) {
        const int s = ck % 3;
        asm volatile("cp.async.wait_group 1;" ::: "memory");
        __syncthreads();

        // Prefetch chunk ck+2 into slot (ck+2)%3 — consumed at ck-1, safe.
        load_chunk(ck + 2, (ck + 2) % 3);

        const uint32_t aA = sb + (uint32_t)s * STAGE;
        const uint32_t aW = aA + A_SZ;

        #pragma unroll
        for (int kk = 0; kk < 4; ++kk) {
            const uint32_t kbA = (uint32_t)((kk * 16 + a_k8) * 2);
            const uint32_t kbB = (uint32_t)((kk * 16 + b_k8) * 2);

            uint32_t bb[8];
            #pragma unroll
            for (int g = 0; g < 2; ++g) {
                uint32_t nn = (uint32_t)(warp_n * 32 + g * 16 + b_row);
                ldsm_x4(bb + g * 4, aW + nn * LD + kbB);
            }
            #pragma unroll
            for (int mt = 0; mt < 4; ++mt) {
                uint32_t m = (uint32_t)(warp_m * 64 + mt * 16 + a_row);
                uint32_t aa[4];
                ldsm_x4(aa, aA + m * LD + kbA);
                #pragma unroll
                for (int nt = 0; nt < 4; ++nt)
                    mma16816(acc[mt][nt], aa, bb + nt * 2);
            }
        }
    }

    // ---- Epilogue 1: write Y ----
    const int er = lane >> 2;
    const int ec = (lane & 3) * 2;
    #pragma unroll
    for (int mt = 0; mt < 4; ++mt) {
        const int row = rowBase + warp_m * 64 + mt * 16 + er;
        #pragma unroll
        for (int nt = 0; nt < 4; ++nt) {
            const int col = colBase + warp_n * 32 + nt * 8 + ec;
            *(float2*)(Y + (size_t)row * CH + col) =
                make_float2(acc[mt][nt][0], acc[mt][nt][1]);
            *(float2*)(Y + (size_t)(row + 8) * CH + col) =
                make_float2(acc[mt][nt][2], acc[mt][nt][3]);
        }
    }

    // ---- Epilogue 2: fused BN stats (sum, sumsq per channel) ----
    #pragma unroll
    for (int nt = 0; nt < 4; ++nt) {
        #pragma unroll
        for (int j = 0; j < 2; ++j) {
            float s = 0.0f, q = 0.0f;
            #pragma unroll
            for (int mt = 0; mt < 4; ++mt) {
                float u0 = acc[mt][nt][j];
                float u1 = acc[mt][nt][j + 2];
                s += u0 + u1;
                q = fmaf(u0, u0, q);
                q = fmaf(u1, u1, q);
            }
            s += __shfl_down_sync(0xffffffffu, s, 16);
            q += __shfl_down_sync(0xffffffffu, q, 16);
            s += __shfl_down_sync(0xffffffffu, s, 8);
            q += __shfl_down_sync(0xffffffffu, q, 8);
            s += __shfl_down_sync(0xffffffffu, s, 4);
            q += __shfl_down_sync(0xffffffffu, q, 4);
            if ((lane >> 2) == 0) {
                int col = colBase + warp_n * 32 + nt * 8 + ec + j;
                atomicAdd(&stats[col], s);
                atomicAdd(&stats[CH + col], q);
            }
        }
    }
}

// ---------------------------------------------------------------------------
// BN+ReLU, output 2-plane bf16 (layer1 -> layer2 input)
// ---------------------------------------------------------------------------
__global__ void __launch_bounds__(256) bnrelu_split_kernel(
    const float* __restrict__ Y,
    const float* __restrict__ gamma, const float* __restrict__ beta,
    __nv_bfloat16* __restrict__ X)
{
    __shared__ float sc[CH], bi[CH];
    const int t = threadIdx.x;
    {
        const float invM = 1.0f / (float)ROWS;
        float mean = g_stats1[t] * invM;
        float var  = g_stats1[CH + t] * invM - mean * mean;
        float s = rsqrtf(var + 1e-5f) * gamma[t];
        sc[t] = s;
        bi[t] = beta[t] - mean * s;
    }
    __syncthreads();

    const int total = ROWS * CH / 4;
    for (int i = blockIdx.x * 256 + t; i < total; i += gridDim.x * 256) {
        float4 v = ((const float4*)Y)[i];
        int row = i >> 6;
        int c0 = (i & 63) * 4;
        float o[4];
        o[0] = fmaxf(fmaf(v.x, sc[c0+0], bi[c0+0]), 0.0f);
        o[1] = fmaxf(fmaf(v.y, sc[c0+1], bi[c0+1]), 0.0f);
        o[2] = fmaxf(fmaf(v.z, sc[c0+2], bi[c0+2]), 0.0f);
        o[3] = fmaxf(fmaf(v.w, sc[c0+3], bi[c0+3]), 0.0f);
        __nv_bfloat16 h[4], l[4];
        #pragma unroll
        for (int j = 0; j < 4; ++j) split_bf16(o[j], h[j], l[j]);
        __nv_bfloat16* base = X + (size_t)row * (2 * CH) + c0;
        *(__nv_bfloat162*)(base)          = __halves2bfloat162(h[0], h[1]);
        *(__nv_bfloat162*)(base + 2)      = __halves2bfloat162(h[2], h[3]);
        *(__nv_bfloat162*)(base + CH)     = __halves2bfloat162(l[0], l[1]);
        *(__nv_bfloat162*)(base + CH + 2) = __halves2bfloat162(l[2], l[3]);
    }
}

// ---------------------------------------------------------------------------
// BN+ReLU in place (layer2 final, fp32)
// ---------------------------------------------------------------------------
__global__ void __launch_bounds__(256) bnrelu_inplace_kernel(
    float* __restrict__ X,
    const float* __restrict__ gamma, const float* __restrict__ beta)
{
    __shared__ float sc[CH], bi[CH];
    const int t = threadIdx.x;
    {
        const float invM = 1.0f / (float)ROWS;
        float mean = g_stats2[t] * invM;
        float var  = g_stats2[CH + t] * invM - mean * mean;
        float s = rsqrtf(var + 1e-5f) * gamma[t];
        sc[t] = s;
        bi[t] = beta[t] - mean * s;
    }
    __syncthreads();

    const int total = ROWS * CH / 4;
    for (int i = blockIdx.x * 256 + t; i < total; i += gridDim.x * 256) {
        float4 v = ((float4*)X)[i];
        int c0 = (i * 4) & (CH - 1);
        v.x = fmaxf(fmaf(v.x, sc[c0+0], bi[c0+0]), 0.0f);
        v.y = fmaxf(fmaf(v.y, sc[c0+1], bi[c0+1]), 0.0f);
        v.z = fmaxf(fmaf(v.z, sc[c0+2], bi[c0+2]), 0.0f);
        v.w = fmaxf(fmaf(v.w, sc[c0+3], bi[c0+3]), 0.0f);
        ((float4*)X)[i] = v;
    }
}

// ---------------------------------------------------------------------------
// Launcher (graph-capturable). Side stream overlaps the conversions with KNN.
// ---------------------------------------------------------------------------
extern "C" void kernel_launch(void* const* d_in, const int* in_sizes, int n_in,
                              void* d_out, int out_size)
{
    const float* p1     = (const float*)d_in[0];
    const float* p2     = (const float*)d_in[1];
    const float* pf1    = (const float*)d_in[2];
    const float* pf2    = (const float*)d_in[3];
    const float* W1     = (const float*)d_in[4];
    const float* gamma1 = (const float*)d_in[5];
    const float* beta1  = (const float*)d_in[6];
    const float* W2     = (const float*)d_in[7];
    const float* gamma2 = (const float*)d_in[8];
    const float* beta2  = (const float*)d_in[9];
    float* out = (float*)d_out;

    __nv_bfloat16 *a1, *x, *w1, *w2;
    float *y, *st1, *st2;
    cudaGetSymbolAddress((void**)&a1, g_a1);
    cudaGetSymbolAddress((void**)&x,  g_x);
    cudaGetSymbolAddress((void**)&w1, g_w1);
    cudaGetSymbolAddress((void**)&w2, g_w2);
    cudaGetSymbolAddress((void**)&y,  g_y);
    cudaGetSymbolAddress((void**)&st1, g_stats1);
    cudaGetSymbolAddress((void**)&st2, g_stats2);

    const int GEMM_SMEM = 3 * 36864;   // 110592 bytes -> 2 CTAs/SM
    cudaFuncSetAttribute(gemm_fused_kernel<CIN>,
                         cudaFuncAttributeMaxDynamicSharedMemorySize, GEMM_SMEM);
    cudaFuncSetAttribute(gemm_fused_kernel<CH>,
                         cudaFuncAttributeMaxDynamicSharedMemorySize, GEMM_SMEM);

    static cudaStream_t side = nullptr;
    static cudaEvent_t evFork = nullptr, evJoin = nullptr;
    if (side == nullptr) {
        cudaStreamCreateWithFlags(&side, cudaStreamNonBlocking);
        cudaEventCreateWithFlags(&evFork, cudaEventDisableTiming);
        cudaEventCreateWithFlags(&evJoin, cudaEventDisableTiming);
    }

    // Fork: side stream joins the (possibly capturing) main stream
    cudaEventRecord(evFork, 0);
    cudaStreamWaitEvent(side, evFork, 0);

    // Side branch: conversions (disjoint from KNN outputs)
    conv_w1_zero_kernel<<<(CH * CIN + 255) / 256, 256, 0, side>>>(W1, w1);
    conv_pf1_kernel<<<ROWS * C1 / 4 / 512, 256, 0, side>>>(pf1, a1);
    conv_w2_kernel<<<(CH * CH + 255) / 256, 256, 0, side>>>(W2, w2);
    cudaEventRecord(evJoin, side);

    // Main branch: KNN + interp (concurrent with conversions)
    knn_interp_kernel<<<dim3(NPTS / 64, BB), 256>>>(p1, p2, pf2, a1);

    // Join
    cudaStreamWaitEvent(0, evJoin, 0);

    // layer-1 GEMM (256 threads, warp tile 64x32 — best measured)
    gemm_fused_kernel<CIN><<<dim3(ROWS / 128, CH / 128), 256, GEMM_SMEM>>>(a1, w1, y, st1);
    // BN+ReLU -> 2-plane x
    bnrelu_split_kernel<<<2048, 256>>>(y, gamma1, beta1, x);
    // layer-2 GEMM -> d_out (pre-activation)
    gemm_fused_kernel<CH><<<dim3(ROWS / 128, CH / 128), 256, GEMM_SMEM>>>(x, w2, out, st2);
    // final BN+ReLU in place
    bnrelu_inplace_kernel<<<2048, 256>>>(out, gamma2, beta2);
}